// round 14
// baseline (speedup 1.0000x reference)
#include <cuda_runtime.h>
#include <cuda_bf16.h>
#include <math.h>
#include <stdint.h>

#define VV   2048
#define EE   512
#define HH   1024
#define BB   128
#define LL   256
#define H3   3072
#define LDEC 255
#define MENC (LL*BB)
#define MDEC (LDEC*BB)
#define EH   (EE+HH)
#define E2H  (EE+2*HH)
#define RGRID 128

#define MT_ENC 256
#define MT_DEC 255
#define KC_GI  24
#define KC_FC  72
#define NT_GI  24
#define NT_FC  16
#define CHB    16384
#define NST    4
#define STB    32768
#define SMEMSZ (1024 + NST*STB)

/* recurrence kernel constants */
#define RNST     4
#define RCH      16384
#define RNCH     32
#define IMGB     ((size_t)RNCH*RCH)
#define RW_BYTES 98304
#define REDST    13                        /* floats per slot (pad: 13 coprime 32) */
#define REDB     (8*4*32*REDST*4)          /* 53248 B */
#define RSM      (1024 + RNST*RCH + RW_BYTES + REDB)

#define SW128(o) ((o) ^ (((o) >> 3) & 0x70))

// ---------------- static scratch ----------------
static __device__ __align__(128) unsigned char g_Xenc_p[(size_t)MT_ENC*KC_GI*CHB];
static __device__ __align__(128) unsigned char g_fcin_p[(size_t)MT_DEC*KC_FC*CHB];
static __device__ __align__(128) unsigned char g_Wihe_p[(size_t)NT_GI*KC_GI*CHB];
static __device__ __align__(128) unsigned char g_Wihd_p[(size_t)NT_GI*KC_GI*CHB];
static __device__ __align__(128) unsigned char g_fcW_p [(size_t)NT_FC*KC_FC*CHB];
static __device__ __align__(128) unsigned char g_WhhE_img[(size_t)RGRID*RW_BYTES];
static __device__ __align__(128) unsigned char g_WhhD_img[(size_t)RGRID*RW_BYTES];
static __device__ __align__(128) unsigned char g_hImg[2*IMGB];

static __device__ float g_gi_enc[(size_t)MENC*H3];
static __device__ float g_gi_dec[(size_t)MDEC*H3];
static __device__ float g_gic[BB*H3];
static __device__ float g_ctx[BB*HH];
static __device__ float g_Pc[BB*VV];
static __device__ unsigned g_arrive;

// ---------------- PTX helpers (baseline PTX only) ----------------
__device__ __forceinline__ uint32_t s2u(const void* p) {
    uint32_t a;
    asm("{ .reg .u64 t; cvta.to.shared.u64 t, %1; cvt.u32.u64 %0, t; }" : "=r"(a) : "l"(p));
    return a;
}
#define MBAR_INIT(a, c) asm volatile("mbarrier.init.shared.b64 [%0], %1;" :: "r"(a), "r"(c) : "memory")
#define MBAR_EXPECT_TX(a, b) asm volatile("mbarrier.arrive.expect_tx.shared.b64 _, [%0], %1;" :: "r"(a), "r"(b) : "memory")
#define MBAR_ARRIVE(a) asm volatile("mbarrier.arrive.shared.b64 _, [%0];" :: "r"(a) : "memory")

#define MBAR_WAIT(a, p) do { \
    uint32_t _m = (a), _p = (p), _d; \
    asm volatile("{\n\t.reg .pred q;\n\tmbarrier.try_wait.parity.acquire.cta.shared::cta.b64 q, [%1], %2;\n\tselp.b32 %0,1,0,q;\n\t}" \
        : "=r"(_d) : "r"(_m), "r"(_p) : "memory"); \
    if (!_d) { \
        asm volatile("{\n\t.reg .pred Q;\n\tWL_%=:\n\tmbarrier.try_wait.parity.acquire.cta.shared::cta.b64 Q, [%0], %1, 0x989680;\n\t@Q bra.uni WD_%=;\n\tbra.uni WL_%=;\n\tWD_%=:\n\t}" \
            :: "r"(_m), "r"(_p) : "memory"); \
    } \
} while (0)

#define MBAR_WAIT_RLX(a, p) do { \
    uint32_t _m = (a), _p = (p), _d; \
    asm volatile("{\n\t.reg .pred q;\n\tmbarrier.try_wait.parity.relaxed.cta.shared::cta.b64 q, [%1], %2, 0x989680;\n\tselp.b32 %0,1,0,q;\n\t}" \
        : "=r"(_d) : "r"(_m), "r"(_p) : "memory"); \
    if (!_d) { \
        asm volatile("{\n\t.reg .pred Q;\n\tWL_%=:\n\tmbarrier.try_wait.parity.relaxed.cta.shared::cta.b64 Q, [%0], %1, 0x989680;\n\t@Q bra.uni WD_%=;\n\tbra.uni WL_%=;\n\tWD_%=:\n\t}" \
            :: "r"(_m), "r"(_p) : "memory"); \
    } \
} while (0)

__device__ __forceinline__ void bulk_g2s(uint32_t dst, const void* src, uint32_t bytes, uint32_t mbar) {
    asm volatile("cp.async.bulk.shared::cluster.global.mbarrier::complete_tx::bytes [%0], [%1], %2, [%3];"
        :: "r"(dst), "l"(src), "r"(bytes), "r"(mbar) : "memory");
}

#define LDSM_X4(r0, r1, r2, r3, a) \
    asm volatile("ldmatrix.sync.aligned.m8n8.x4.shared.b16 {%0,%1,%2,%3}, [%4];" \
        : "=r"(r0), "=r"(r1), "=r"(r2), "=r"(r3) : "r"(a))
#define LDSM_X2(r0, r1, a) \
    asm volatile("ldmatrix.sync.aligned.m8n8.x2.shared.b16 {%0,%1}, [%2];" \
        : "=r"(r0), "=r"(r1) : "r"(a))

#define MMA16816(d, a0, a1, a2, a3, b0, b1) \
    asm volatile("mma.sync.aligned.m16n8k16.row.col.f32.bf16.bf16.f32 " \
        "{%0,%1,%2,%3}, {%4,%5,%6,%7}, {%8,%9}, {%0,%1,%2,%3};" \
        : "+f"((d)[0]), "+f"((d)[1]), "+f"((d)[2]), "+f"((d)[3]) \
        : "r"(a0), "r"(a1), "r"(a2), "r"(a3), "r"(b0), "r"(b1))

// fast gates (MUFU-based; ~2ulp, far below split error)
__device__ __forceinline__ float fast_sigmoid(float x) {
    return 1.f / (1.f + __expf(-x));
}
__device__ __forceinline__ float fast_tanh(float x) {
    float a = fminf(fmaxf(x, -15.f), 15.f);
    float e = __expf(-2.f * a);
    return (1.f - e) / (1.f + e);
}

// ---------------- tiny helpers ----------------
__global__ void k_reset_bar() { g_arrive = 0u; }

// ---------------- bf16 split + SW128 packing ----------------
__device__ __forceinline__ void split8(const float* a, uint4& H, uint4& L) {
    unsigned hv[4], lv[4];
#pragma unroll
    for (int j = 0; j < 4; j++) {
        __nv_bfloat16 h0 = __float2bfloat16(a[2*j]),   h1 = __float2bfloat16(a[2*j+1]);
        __nv_bfloat16 l0 = __float2bfloat16(a[2*j]   - __bfloat162float(h0));
        __nv_bfloat16 l1 = __float2bfloat16(a[2*j+1] - __bfloat162float(h1));
        hv[j] = (unsigned)__bfloat16_as_ushort(h0) | ((unsigned)__bfloat16_as_ushort(h1) << 16);
        lv[j] = (unsigned)__bfloat16_as_ushort(l0) | ((unsigned)__bfloat16_as_ushort(l1) << 16);
    }
    H = make_uint4(hv[0], hv[1], hv[2], hv[3]);
    L = make_uint4(lv[0], lv[1], lv[2], lv[3]);
}

__global__ void k_pack_X(const float* __restrict__ emb, const int* __restrict__ seq,
                         unsigned char* __restrict__ dst, int Mrows, int ACH) {
    int i = blockIdx.x * blockDim.x + threadIdx.x;
    int m = i >> 6;
    if (m >= Mrows) return;
    int k = (i & 63) * 8;
    int tok = seq[(m & 127) * LL + (m >> 7)];
    const float* s = emb + (size_t)tok * EE + k;
    float4 f0 = *(const float4*)s, f1 = *(const float4*)(s + 4);
    float a[8] = {f0.x, f0.y, f0.z, f0.w, f1.x, f1.y, f1.z, f1.w};
    uint4 H, L; split8(a, H, L);
    int mt = m >> 7, r = m & 127;
    int sw = SW128(r*128 + (k & 63)*2);
    int c0 = k >> 6;
    size_t tb = (size_t)mt * ACH * CHB;
    *(uint4*)(dst + tb + (size_t)(c0     ) * CHB + sw) = H;
    *(uint4*)(dst + tb + (size_t)(c0 + 8 ) * CHB + sw) = L;
    *(uint4*)(dst + tb + (size_t)(c0 + 16) * CHB + sw) = H;
}

__device__ __forceinline__ void packW_item(int i, const float* __restrict__ W, int ldw, int col0,
                                           unsigned char* __restrict__ dst, int Ksrc,
                                           int chunkbase, int KCtot) {
    int Kvec = Ksrc >> 3;
    int n = i / Kvec;
    int k = (i - n * Kvec) * 8;
    const float* s = W + (size_t)n * ldw + col0 + k;
    float4 f0 = *(const float4*)s, f1 = *(const float4*)(s + 4);
    float a[8] = {f0.x, f0.y, f0.z, f0.w, f1.x, f1.y, f1.z, f1.w};
    uint4 H, L; split8(a, H, L);
    int nt = n >> 7, r = n & 127;
    int sw = SW128(r*128 + (k & 63)*2);
    int c0 = k >> 6, KS = Ksrc >> 6;
    size_t tb = (size_t)nt * KCtot * CHB;
    *(uint4*)(dst + tb + (size_t)(chunkbase + c0        ) * CHB + sw) = H;
    *(uint4*)(dst + tb + (size_t)(chunkbase + KS + c0   ) * CHB + sw) = H;
    *(uint4*)(dst + tb + (size_t)(chunkbase + 2*KS + c0 ) * CHB + sw) = L;
}

__device__ __forceinline__ void packWhh_item(int i, const float* __restrict__ Whh,
                                             unsigned char* __restrict__ img) {
    int n = i >> 7;
    int k = (i & 127) * 8;
    int g = n >> 10, hcol = n & 1023;
    int blk = hcol >> 3, jj = hcol & 7;
    int rr = g*8 + jj;
    const float* s = Whh + (size_t)n * HH + k;
    float4 f0 = *(const float4*)s, f1 = *(const float4*)(s + 4);
    float a[8] = {f0.x, f0.y, f0.z, f0.w, f1.x, f1.y, f1.z, f1.w};
    uint4 H, L; split8(a, H, L);
    unsigned char* base = img + (size_t)blk * RW_BYTES;
    int sw = SW128(rr*128 + (k & 63)*2);
    *(uint4*)(base + (size_t)(k >> 6) * 3072 + sw) = H;
    *(uint4*)(base + (size_t)(16 + (k >> 6)) * 3072 + sw) = L;
}

// All weight packs in ONE launch.
#define J0 196608
#define J1 393216
#define J2 524288
#define J3 786432
#define J4 1179648
#define J5 1572864
__global__ void k_pack_Wall(const float* __restrict__ Wihe, const float* __restrict__ Wihd,
                            const float* __restrict__ fcW,
                            const float* __restrict__ WhhE, const float* __restrict__ WhhD,
                            unsigned char* __restrict__ WiheP, unsigned char* __restrict__ WihdP,
                            unsigned char* __restrict__ fcWP,
                            unsigned char* __restrict__ WhhEimg, unsigned char* __restrict__ WhhDimg) {
    int i = blockIdx.x * blockDim.x + threadIdx.x;
    if (i < J0)      { packW_item(i,      Wihe, EE,  0,  WiheP, EE, 0,  KC_GI); }
    else if (i < J1) { packW_item(i - J0, Wihd, EH,  0,  WihdP, EE, 0,  KC_GI); }
    else if (i < J2) { packW_item(i - J1, fcW,  E2H, 0,  fcWP,  EE, 0,  KC_FC); }
    else if (i < J3) { packW_item(i - J2, fcW,  E2H, EE, fcWP,  HH, 24, KC_FC); }
    else if (i < J4) { packWhh_item(i - J3, WhhE, WhhEimg); }
    else if (i < J5) { packWhh_item(i - J4, WhhD, WhhDimg); }
}

// ---------------- mma.sync bf16 GEMM (R8-proven: NST=4, 1 CTA/SM) ----------------
__global__ __launch_bounds__(288, 1)
void k_mmagemm(const unsigned char* __restrict__ Ap, int ACH,
               const unsigned char* __restrict__ Bp, int KC,
               const float* __restrict__ bias, float* __restrict__ C, int ldc,
               const float* __restrict__ Pc, float* __restrict__ outp, int mode) {
    extern __shared__ unsigned char smem[];
    uint32_t sb = s2u(smem);
    int tid = threadIdx.x, wid = tid >> 5, lane = tid & 31;
    int nt = blockIdx.x, mt = blockIdx.y;

    if (tid == 0) {
        for (int s = 0; s < NST; s++) { MBAR_INIT(sb + 8 + s*8, 1); MBAR_INIT(sb + 40 + s*8, 8); }
    }
    __syncthreads();

    const unsigned char* Ab = Ap + (size_t)mt * ACH * CHB;
    const unsigned char* Bb = Bp + (size_t)nt * KC * CHB;

    if (wid == 8) {
        if (lane == 0) {
            for (int kc = 0; kc < KC; kc++) {
                int s = kc & (NST - 1);
                int eph = (((kc >> 2) & 1)) ^ 1;
                MBAR_WAIT_RLX(sb + 40 + s*8, eph);
                MBAR_EXPECT_TX(sb + 8 + s*8, 2*CHB);
                bulk_g2s(sb + 1024 + s*STB,       Ab + (size_t)kc*CHB, CHB, sb + 8 + s*8);
                bulk_g2s(sb + 1024 + s*STB + CHB, Bb + (size_t)kc*CHB, CHB, sb + 8 + s*8);
            }
        }
        return;
    }

    int wm = wid & 1, wn = wid >> 1;
    float d[4][4][4];
#pragma unroll
    for (int i = 0; i < 4; i++)
#pragma unroll
        for (int j = 0; j < 4; j++)
#pragma unroll
            for (int q = 0; q < 4; q++) d[i][j][q] = 0.f;

    int arow = lane & 15;
    int ahalf = (lane >> 4) * 16;
    int axm = (arow & 7) << 4;
    uint32_t aRow128[4];
#pragma unroll
    for (int i = 0; i < 4; i++) aRow128[i] = (uint32_t)(wm*64 + i*16 + arow) * 128;
    int bg = lane >> 3;
    int bn7 = lane & 7;
    int bxm = bn7 << 4;
    int bkadd = (bg & 1) * 16;
    uint32_t bRow128[2];
#pragma unroll
    for (int q = 0; q < 2; q++) bRow128[q] = (uint32_t)(wn*32 + q*16 + (bg>>1)*8 + bn7) * 128;

    for (int kc = 0; kc < KC; kc++) {
        int s = kc & (NST - 1);
        int ph = (kc >> 2) & 1;
        MBAR_WAIT(sb + 8 + s*8, ph);
        uint32_t Abase = sb + 1024 + s*STB;
        uint32_t Bbase = Abase + CHB;
#pragma unroll
        for (int ks = 0; ks < 4; ks++) {
            int kb = ks * 32;
            uint32_t afr[4][4], bfr[2][4];
#pragma unroll
            for (int i = 0; i < 4; i++) {
                uint32_t addr = Abase + aRow128[i] + (uint32_t)((kb + ahalf) ^ axm);
                LDSM_X4(afr[i][0], afr[i][1], afr[i][2], afr[i][3], addr);
            }
#pragma unroll
            for (int q = 0; q < 2; q++) {
                uint32_t addr = Bbase + bRow128[q] + (uint32_t)((kb + bkadd) ^ bxm);
                LDSM_X4(bfr[q][0], bfr[q][1], bfr[q][2], bfr[q][3], addr);
            }
#pragma unroll
            for (int i = 0; i < 4; i++)
#pragma unroll
                for (int j = 0; j < 4; j++)
                    MMA16816(d[i][j], afr[i][0], afr[i][1], afr[i][2], afr[i][3],
                             bfr[j>>1][(j&1)*2], bfr[j>>1][(j&1)*2 + 1]);
        }
        __syncwarp();
        if (lane == 0) MBAR_ARRIVE(sb + 40 + s*8);
    }

    int lr = lane >> 2;
    int lc = (lane & 3) * 2;
#pragma unroll
    for (int i = 0; i < 4; i++) {
        int r0 = wm*64 + i*16 + lr;
#pragma unroll
        for (int j = 0; j < 4; j++) {
            int c = nt*128 + wn*32 + j*8 + lc;
            if (mode == 0) {
                float2 bv = *(const float2*)(bias + c);
                float* cp0 = C + (size_t)(mt*128 + r0) * ldc + c;
                float* cp1 = C + (size_t)(mt*128 + r0 + 8) * ldc + c;
                *(float2*)cp0 = make_float2(d[i][j][0] + bv.x, d[i][j][1] + bv.y);
                *(float2*)cp1 = make_float2(d[i][j][2] + bv.x, d[i][j][3] + bv.y);
            } else {
                float2 p0 = *(const float2*)(Pc + (size_t)r0 * VV + c);
                float2 p1 = *(const float2*)(Pc + (size_t)(r0 + 8) * VV + c);
                float* op0 = outp + ((size_t)r0 * LL + (mt + 1)) * VV + c;
                float* op1 = outp + ((size_t)(r0 + 8) * LL + (mt + 1)) * VV + c;
                *(float2*)op0 = make_float2(d[i][j][0] + p0.x, d[i][j][1] + p0.y);
                *(float2*)op1 = make_float2(d[i][j][2] + p1.x, d[i][j][3] + p1.y);
            }
        }
    }
}

// ---------------- small fp32 GEMM (context one-shots) ----------------
__global__ __launch_bounds__(256) void k_gemm(
    const float* __restrict__ A, int lda,
    const float* __restrict__ Bw, int ldb, int bofs,
    const float* __restrict__ bias,
    float* __restrict__ C, int N, int K)
{
    __shared__ float As[16][132];
    __shared__ float Bs[16][68];
    const int m0 = blockIdx.y * 128;
    const int n0 = blockIdx.x * 64;
    const int tid = threadIdx.x;
    const int rg = tid >> 4, cg = tid & 15;
    float acc[8][4];
#pragma unroll
    for (int i = 0; i < 8; i++)
#pragma unroll
        for (int j = 0; j < 4; j++) acc[i][j] = 0.f;
    const int r0 = tid >> 2, r1 = r0 + 64;
    const int kq0 = (tid & 3) * 4;
    const size_t aoff0 = (size_t)(m0+r0) * lda;
    const size_t aoff1 = (size_t)(m0+r1) * lda;
    const size_t boff  = (size_t)(n0 + r0) * ldb + bofs;
    for (int k0 = 0; k0 < K; k0 += 16) {
        float4 va0 = *reinterpret_cast<const float4*>(A + aoff0 + k0 + kq0);
        float4 va1 = *reinterpret_cast<const float4*>(A + aoff1 + k0 + kq0);
        float4 vb  = *reinterpret_cast<const float4*>(Bw + boff + k0 + kq0);
        As[kq0+0][r0] = va0.x; As[kq0+1][r0] = va0.y; As[kq0+2][r0] = va0.z; As[kq0+3][r0] = va0.w;
        As[kq0+0][r1] = va1.x; As[kq0+1][r1] = va1.y; As[kq0+2][r1] = va1.z; As[kq0+3][r1] = va1.w;
        Bs[kq0+0][r0] = vb.x;  Bs[kq0+1][r0] = vb.y;  Bs[kq0+2][r0] = vb.z;  Bs[kq0+3][r0] = vb.w;
        __syncthreads();
#pragma unroll
        for (int kk = 0; kk < 16; kk++) {
            float4 a0 = *reinterpret_cast<const float4*>(&As[kk][rg*8]);
            float4 a1 = *reinterpret_cast<const float4*>(&As[kk][rg*8+4]);
            float4 b  = *reinterpret_cast<const float4*>(&Bs[kk][cg*4]);
            float av[8] = {a0.x,a0.y,a0.z,a0.w,a1.x,a1.y,a1.z,a1.w};
            float bv[4] = {b.x,b.y,b.z,b.w};
#pragma unroll
            for (int i = 0; i < 8; i++)
#pragma unroll
                for (int j = 0; j < 4; j++) acc[i][j] += av[i]*bv[j];
        }
        __syncthreads();
    }
    float4 bb = make_float4(0.f,0.f,0.f,0.f);
    if (bias) bb = *reinterpret_cast<const float4*>(bias + n0 + cg*4);
#pragma unroll
    for (int i = 0; i < 8; i++) {
        float* cp = C + (size_t)(m0 + rg*8 + i) * N + n0 + cg*4;
        *reinterpret_cast<float4*>(cp) =
            make_float4(acc[i][0]+bb.x, acc[i][1]+bb.y, acc[i][2]+bb.z, acc[i][3]+bb.w);
    }
}

// ---------------- grid barrier (128 arrivals) ----------------
__device__ __forceinline__ void grid_bar(unsigned want) {
    __threadfence();
    __syncthreads();
    if (threadIdx.x == 0) {
        atomicAdd(&g_arrive, 1u);
        volatile unsigned* p = &g_arrive;
        while (*p < want) { }
    }
    __syncthreads();
}

// ---------------- tensor-core persistent GRU recurrence (4-way K-split) ----------------
// 128 blocks x 288 threads: 8 compute warps + producer warp 8.
// Warp quad (4p..4p+3) owns batch rows p*64..p*64+63; each warp processes only
// chunks with (c & 3) == (wid & 3) (8 chunks), so each W frag is read by 2 warps.
// Stage s = c&3 = wid&3 -> each empty mbar has exactly 2 consumers.
// Accumulator frags exchanged via smem (stride-13 slots, conflict-free).
__global__ __launch_bounds__(288, 1)
void k_rec_tc(const unsigned char* __restrict__ Wimg,
              const float* __restrict__ gi, const float* __restrict__ gic,
              unsigned char* __restrict__ imgBase,
              const float* __restrict__ bhh,
              const float* __restrict__ ctx_init,
              float* __restrict__ ctx_out,
              unsigned char* __restrict__ fcpack,
              int T)
{
    extern __shared__ unsigned char smem[];
    uint32_t sb = s2u(smem);
    int tid = threadIdx.x, wid = tid >> 5, lane = tid & 31;
    int bid = blockIdx.x;
    int j0 = bid * 8;
    int sub = wid & 3;
    int quad = (wid >> 2) & 1;

    if (tid == 0) {
        for (int s = 0; s < RNST; s++) { MBAR_INIT(sb + 16 + s*8, 1); MBAR_INIT(sb + 80 + s*8, 2); }
        MBAR_INIT(sb + 144, 1);
    }
    __syncthreads();

    uint32_t ringb = sb + 1024;
    uint32_t wsm   = sb + 1024 + RNST*RCH;
    float*   red   = (float*)(smem + 1024 + RNST*RCH + RW_BYTES);

    if (wid == 8 && lane == 0) {
        MBAR_EXPECT_TX(sb + 144, RW_BYTES);
        bulk_g2s(wsm, Wimg + (size_t)bid * RW_BYTES, RW_BYTES, sb + 144);
    }

    int lr = lane >> 2, lc2 = (lane & 3) * 2;
    int chnk = j0 >> 6;
    int cbyte = ((j0 + lc2) & 63) * 2;
    float ho[2][2];
    float2 gx[2][3];
    float2 bh2[3];

    if (wid < 8) {
#pragma unroll
        for (int g = 0; g < 3; g++) bh2[g] = *(const float2*)(bhh + g*HH + j0 + lc2);
#pragma unroll
        for (int h = 0; h < 2; h++) {
            int b = wid*16 + h*8 + lr;
            if (ctx_init) {
                float2 c = __ldcg((const float2*)(ctx_init + (size_t)b*HH + j0 + lc2));
                ho[h][0] = c.x; ho[h][1] = c.y;
            } else { ho[h][0] = 0.f; ho[h][1] = 0.f; }
            if (gic) {
#pragma unroll
                for (int g = 0; g < 3; g++)
                    gx[h][g] = *(const float2*)(gic + (size_t)b*H3 + g*HH + j0 + lc2);
            } else {
#pragma unroll
                for (int g = 0; g < 3; g++) gx[h][g] = make_float2(0.f, 0.f);
            }
            if (!ctx_init) {
                unsigned sw = SW128((unsigned)(b*128 + cbyte));
                __stcg((unsigned*)(imgBase + (size_t)chnk*RCH + sw), 0u);
                __stcg((unsigned*)(imgBase + (size_t)(16+chnk)*RCH + sw), 0u);
            }
        }
    }
    grid_bar(1u * RGRID);
    if (wid < 8) MBAR_WAIT(sb + 144, 0);

    int arow = lane & 15, ahalf = (lane >> 4) * 16, axm = (arow & 7) << 4;
    uint32_t aR[4];
#pragma unroll
    for (int i = 0; i < 4; i++)
        aR[i] = (uint32_t)(quad*64 + i*16 + arow) * 128;  // (garbage for wid==8, unused)
    int b4row = (lane >> 4)*8 + (lane & 7);
    int b4k   = ((lane >> 3) & 1) * 16;
    int b4xm  = (b4row & 7) << 4;
    int b2row = 16 + (lane & 7);
    int b2k   = ((lane >> 3) & 1) * 16;
    int b2xm  = (b2row & 7) << 4;

    for (int t = 0; t < T; t++) {
        const unsigned char* img_r = imgBase + (size_t)(t & 1) * IMGB;
        unsigned char*       img_w = imgBase + (size_t)((t + 1) & 1) * IMGB;

        if (wid == 8) {
            if (lane == 0) {
                for (int c = 0; c < RNCH; c++) {
                    unsigned idx = (unsigned)t * RNCH + c;
                    int s = idx & (RNST - 1);
                    int eph = ((idx >> 2) & 1) ^ 1;
                    MBAR_WAIT_RLX(sb + 80 + s*8, eph);
                    MBAR_EXPECT_TX(sb + 16 + s*8, RCH);
                    bulk_g2s(ringb + s*RCH, img_r + (size_t)c*RCH, RCH, sb + 16 + s*8);
                }
            }
        } else {
            float2 gv[2][3];
#pragma unroll
            for (int h = 0; h < 2; h++) {
                int b = wid*16 + h*8 + lr;
                const float* gb = gi + ((size_t)t*BB + b)*H3 + j0 + lc2;
#pragma unroll
                for (int g = 0; g < 3; g++)
                    gv[h][g] = __ldcg((const float2*)(gb + g*HH));
            }

            float d[4][3][4];
#pragma unroll
            for (int i = 0; i < 4; i++)
#pragma unroll
                for (int nf = 0; nf < 3; nf++)
#pragma unroll
                    for (int q = 0; q < 4; q++) d[i][nf][q] = 0.f;

            // process only chunks with (c & 3) == sub; stage is always == sub
            for (int c = sub; c < RNCH; c += 4) {
                unsigned idx = (unsigned)t * RNCH + c;
                int s = sub;
                int fph = (idx >> 2) & 1;
                MBAR_WAIT(sb + 16 + s*8, fph);
                uint32_t Abase = ringb + s*RCH;
                int cw = (c < 16) ? c : (c - 16);
                uint32_t Wh = wsm + (uint32_t)cw * 3072;
#pragma unroll
                for (int ks = 0; ks < 4; ks++) {
                    int kb = ks * 32;
                    uint32_t a0[4], a1[4], a2[4], a3[4];
#pragma unroll
                    for (int i = 0; i < 4; i++)
                        LDSM_X4(a0[i], a1[i], a2[i], a3[i],
                                Abase + aR[i] + (uint32_t)((kb + ahalf) ^ axm));
                    uint32_t b0,b1,b2,b3,b4,b5;
                    LDSM_X4(b0,b1,b2,b3, Wh + (uint32_t)(b4row*128) + (uint32_t)((kb + b4k) ^ b4xm));
                    LDSM_X2(b4,b5,       Wh + (uint32_t)(b2row*128) + (uint32_t)((kb + b2k) ^ b2xm));
#pragma unroll
                    for (int i = 0; i < 4; i++) {
                        MMA16816(d[i][0], a0[i], a1[i], a2[i], a3[i], b0, b1);
                        MMA16816(d[i][1], a0[i], a1[i], a2[i], a3[i], b2, b3);
                        MMA16816(d[i][2], a0[i], a1[i], a2[i], a3[i], b4, b5);
                    }
                    if (c < 16) {
                        uint32_t Wl = wsm + (uint32_t)(16 + c) * 3072;
                        LDSM_X4(b0,b1,b2,b3, Wl + (uint32_t)(b4row*128) + (uint32_t)((kb + b4k) ^ b4xm));
                        LDSM_X2(b4,b5,       Wl + (uint32_t)(b2row*128) + (uint32_t)((kb + b2k) ^ b2xm));
#pragma unroll
                        for (int i = 0; i < 4; i++) {
                            MMA16816(d[i][0], a0[i], a1[i], a2[i], a3[i], b0, b1);
                            MMA16816(d[i][1], a0[i], a1[i], a2[i], a3[i], b2, b3);
                            MMA16816(d[i][2], a0[i], a1[i], a2[i], a3[i], b4, b5);
                        }
                    }
                }
                __syncwarp();
                if (lane == 0) MBAR_ARRIVE(sb + 80 + s*8);
            }

            // exchange: give frag p (p != sub) to quad partner with sub==p.
            // slot layout: red[(dest_wid*4 + src_sub)*32 + lane] * REDST floats.
            {
                int qbase = wid & ~3;
#pragma unroll
                for (int p2 = 0; p2 < 4; p2++) {
                    if (p2 == sub) continue;
                    float* wr = red + (size_t)(((qbase + p2)*4 + sub)*32 + lane) * REDST;
#pragma unroll
                    for (int nf = 0; nf < 3; nf++)
#pragma unroll
                        for (int q = 0; q < 4; q++)
                            wr[nf*4 + q] = d[p2][nf][q];
                }
            }
            asm volatile("bar.sync 1, 256;" ::: "memory");
            float dd[3][4];
#pragma unroll
            for (int nf = 0; nf < 3; nf++)
#pragma unroll
                for (int q = 0; q < 4; q++) dd[nf][q] = d[sub][nf][q];
#pragma unroll
            for (int src = 0; src < 4; src++) {
                if (src == sub) continue;
                const float* pr = red + (size_t)((wid*4 + src)*32 + lane) * REDST;
#pragma unroll
                for (int nf = 0; nf < 3; nf++)
#pragma unroll
                    for (int q = 0; q < 4; q++)
                        dd[nf][q] += pr[nf*4 + q];
            }

            // GRU elementwise (fast MUFU gates); critical-path img stores first
            unsigned hiw_s[2], low_s[2];
#pragma unroll
            for (int h = 0; h < 2; h++) {
#pragma unroll
                for (int c2 = 0; c2 < 2; c2++) {
                    int q = h*2 + c2;
                    float gr = (c2 ? gv[h][0].y : gv[h][0].x) + (c2 ? gx[h][0].y : gx[h][0].x);
                    float gz = (c2 ? gv[h][1].y : gv[h][1].x) + (c2 ? gx[h][1].y : gx[h][1].x);
                    float gn = (c2 ? gv[h][2].y : gv[h][2].x) + (c2 ? gx[h][2].y : gx[h][2].x);
                    float hr = dd[0][q] + (c2 ? bh2[0].y : bh2[0].x);
                    float hz = dd[1][q] + (c2 ? bh2[1].y : bh2[1].x);
                    float hn = dd[2][q] + (c2 ? bh2[2].y : bh2[2].x);
                    float rr = fast_sigmoid(gr + hr);
                    float zz = fast_sigmoid(gz + hz);
                    float nn = fast_tanh(gn + rr * hn);
                    ho[h][c2] = (1.f - zz) * nn + zz * ho[h][c2];
                }
                __nv_bfloat16 h0b = __float2bfloat16(ho[h][0]);
                __nv_bfloat16 h1b = __float2bfloat16(ho[h][1]);
                __nv_bfloat16 l0b = __float2bfloat16(ho[h][0] - __bfloat162float(h0b));
                __nv_bfloat16 l1b = __float2bfloat16(ho[h][1] - __bfloat162float(h1b));
                unsigned hiw = (unsigned)__bfloat16_as_ushort(h0b) | ((unsigned)__bfloat16_as_ushort(h1b) << 16);
                unsigned low = (unsigned)__bfloat16_as_ushort(l0b) | ((unsigned)__bfloat16_as_ushort(l1b) << 16);
                int b = wid*16 + h*8 + lr;
                unsigned sw = SW128((unsigned)(b*128 + cbyte));
                __stcg((unsigned*)(img_w + (size_t)chnk*RCH + sw), hiw);
                __stcg((unsigned*)(img_w + (size_t)(16+chnk)*RCH + sw), low);
                hiw_s[h] = hiw; low_s[h] = low;
            }
#pragma unroll
            for (int h = 0; h < 2; h++) {
                int b = wid*16 + h*8 + lr;
                unsigned sw = SW128((unsigned)(b*128 + cbyte));
                if (fcpack) {
                    size_t tb2 = (size_t)t * KC_FC * CHB;
                    __stcg((unsigned*)(fcpack + tb2 + (size_t)(24+chnk)*CHB + sw), hiw_s[h]);
                    __stcg((unsigned*)(fcpack + tb2 + (size_t)(40+chnk)*CHB + sw), low_s[h]);
                    __stcg((unsigned*)(fcpack + tb2 + (size_t)(56+chnk)*CHB + sw), hiw_s[h]);
                }
                if (ctx_out && t == T-1)
                    __stcg((float2*)(ctx_out + (size_t)b*HH + j0 + lc2),
                           make_float2(ho[h][0], ho[h][1]));
            }
        }
        grid_bar((unsigned)(t + 2) * RGRID);
    }
}

// ---------------- small output pieces ----------------
__global__ void k_out_small(float* __restrict__ out) {
    int i = blockIdx.x * blockDim.x + threadIdx.x;
    const size_t NOUT = (size_t)BB * LL * VV;
    if (i < BB * VV) {
        int b = i / VV, v = i % VV;
        out[(size_t)b * LL * VV + v] = 0.f;
    }
    if (i < 3 * BB * HH) {
        out[NOUT + i] = (i < BB * HH) ? g_ctx[i] : 0.f;
    }
}

// ---------------- launch ----------------
extern "C" void kernel_launch(void* const* d_in, const int* in_sizes, int n_in,
                              void* d_out, int out_size) {
    const int*   seq     = (const int*)  d_in[0];
    const float* emb_enc = (const float*)d_in[2];
    const float* W_ih_e  = (const float*)d_in[3];
    const float* W_hh_e  = (const float*)d_in[4];
    const float* b_ih_e  = (const float*)d_in[5];
    const float* b_hh_e  = (const float*)d_in[6];
    const float* emb_dec = (const float*)d_in[7];
    const float* W_ih_d  = (const float*)d_in[8];
    const float* W_hh_d  = (const float*)d_in[9];
    const float* b_ih_d  = (const float*)d_in[10];
    const float* b_hh_d  = (const float*)d_in[11];
    const float* fc_W    = (const float*)d_in[12];
    const float* fc_b    = (const float*)d_in[13];

    void* p;
    cudaGetSymbolAddress(&p, g_gi_enc);  float* gi_enc = (float*)p;
    cudaGetSymbolAddress(&p, g_gi_dec);  float* gi_dec = (float*)p;
    cudaGetSymbolAddress(&p, g_gic);     float* gic = (float*)p;
    cudaGetSymbolAddress(&p, g_ctx);     float* ctx = (float*)p;
    cudaGetSymbolAddress(&p, g_Pc);      float* Pc = (float*)p;
    cudaGetSymbolAddress(&p, g_Xenc_p);  unsigned char* Xenc_p = (unsigned char*)p;
    cudaGetSymbolAddress(&p, g_fcin_p);  unsigned char* fcin_p = (unsigned char*)p;
    cudaGetSymbolAddress(&p, g_Wihe_p);  unsigned char* Wihe_p = (unsigned char*)p;
    cudaGetSymbolAddress(&p, g_Wihd_p);  unsigned char* Wihd_p = (unsigned char*)p;
    cudaGetSymbolAddress(&p, g_fcW_p);   unsigned char* fcW_p = (unsigned char*)p;
    cudaGetSymbolAddress(&p, g_WhhE_img); unsigned char* WhhE = (unsigned char*)p;
    cudaGetSymbolAddress(&p, g_WhhD_img); unsigned char* WhhD = (unsigned char*)p;
    cudaGetSymbolAddress(&p, g_hImg);     unsigned char* hImg = (unsigned char*)p;

    cudaFuncSetAttribute(k_mmagemm, cudaFuncAttributeMaxDynamicSharedMemorySize, SMEMSZ);
    cudaFuncSetAttribute(k_rec_tc,  cudaFuncAttributeMaxDynamicSharedMemorySize, RSM);

    static cudaStream_t s2 = nullptr;
    static cudaEvent_t e1 = nullptr, e2 = nullptr;
    if (!s2) {
        cudaStreamCreateWithFlags(&s2, cudaStreamNonBlocking);
        cudaEventCreateWithFlags(&e1, cudaEventDisableTiming);
        cudaEventCreateWithFlags(&e2, cudaEventDisableTiming);
    }

    // 0,1) input packs
    k_pack_X<<<(MENC*64 + 255)/256, 256>>>(emb_enc, seq, Xenc_p, MENC, KC_GI);
    k_pack_X<<<(MDEC*64 + 255)/256, 256>>>(emb_dec, seq, fcin_p, MDEC, KC_FC);
    // 2) all weight packs
    k_pack_Wall<<<(J5 + 255)/256, 256>>>(W_ih_e, W_ih_d, fc_W, W_hh_e, W_hh_d,
                                         Wihe_p, Wihd_p, fcW_p, WhhE, WhhD);
    // 3) encoder input-gate GEMM
    k_mmagemm<<<dim3(NT_GI, MT_ENC), 288, SMEMSZ>>>(Xenc_p, KC_GI, Wihe_p, KC_GI, b_ih_e, gi_enc, H3, nullptr, nullptr, 0);
    // 4) barrier reset
    k_reset_bar<<<1, 1>>>();
    cudaEventRecord(e1, 0);

    // 5) encoder recurrence FIRST (grid=128 lands on SMs immediately)
    k_rec_tc<<<RGRID, 288, RSM>>>(WhhE, gi_enc, nullptr, hImg, b_hh_e, nullptr, ctx, nullptr, LL);

    // Fork: decoder input-gate GEMM in s2 fills the ~20 SMs the rec leaves free.
    cudaStreamWaitEvent(s2, e1, 0);
    k_mmagemm<<<dim3(NT_GI, MT_DEC), 288, SMEMSZ, s2>>>(fcin_p, KC_FC, Wihd_p, KC_GI, b_ih_d, gi_dec, H3, nullptr, nullptr, 0);
    cudaEventRecord(e2, s2);

    // 6,7) context one-shots (depend on enc rec only)
    k_gemm<<<dim3(H3/64, 1), 256>>>(ctx, HH, W_ih_d, EH, EE, nullptr, gic, H3, HH);
    k_gemm<<<dim3(VV/64, 1), 256>>>(ctx, HH, fc_W, E2H, EE + HH, fc_b, Pc, VV, HH);
    // 8) barrier reset
    k_reset_bar<<<1, 1>>>();

    // Join: decoder recurrence consumes gi_dec produced in s2.
    cudaStreamWaitEvent(0, e2, 0);
    // 9) decoder recurrence (packs h2 into fcin chunks 24..71)
    k_rec_tc<<<RGRID, 288, RSM>>>(WhhD, gi_dec, gic, hImg, b_hh_d, ctx, nullptr, fcin_p, LDEC);
    // 10) fused fc GEMM -> d_out
    k_mmagemm<<<dim3(NT_FC, MT_DEC), 288, SMEMSZ>>>(fcin_p, KC_FC, fcW_p, KC_FC, nullptr, nullptr, 0, Pc, (float*)d_out, 1);
    // 11) small output pieces
    k_out_small<<<(3*BB*HH + 255)/256, 256>>>((float*)d_out);
}

// round 15
// speedup vs baseline: 4.3581x; 4.3581x over previous
#include <cuda_runtime.h>
#include <cuda_bf16.h>
#include <math.h>
#include <stdint.h>

#define VV   2048
#define EE   512
#define HH   1024
#define BB   128
#define LL   256
#define H3   3072
#define LDEC 255
#define MENC (LL*BB)
#define MDEC (LDEC*BB)
#define EH   (EE+HH)
#define E2H  (EE+2*HH)
#define RGRID 128

#define MT_ENC 256
#define MT_DEC 255
#define KC_GI  24
#define KC_FC  72
#define NT_GI  24
#define NT_FC  16
#define CHB    16384
#define NST    4
#define STB    32768
#define SMEMSZ (1024 + NST*STB)

/* recurrence kernel constants (R13-proven: 2-way K-split, ring depth 4) */
#define RNST     4
#define RCH      16384
#define RNCH     32
#define IMGB     ((size_t)RNCH*RCH)
#define RW_BYTES 98304
#define REDB     12288                     /* 8 warps x 32 lanes x 12 floats */
#define RSM      (1024 + RNST*RCH + RW_BYTES + REDB)

#define SW128(o) ((o) ^ (((o) >> 3) & 0x70))

// ---------------- static scratch ----------------
static __device__ __align__(128) unsigned char g_Xenc_p[(size_t)MT_ENC*KC_GI*CHB];
static __device__ __align__(128) unsigned char g_fcin_p[(size_t)MT_DEC*KC_FC*CHB];
static __device__ __align__(128) unsigned char g_Wihe_p[(size_t)NT_GI*KC_GI*CHB];
static __device__ __align__(128) unsigned char g_Wihd_p[(size_t)NT_GI*KC_GI*CHB];
static __device__ __align__(128) unsigned char g_fcW_p [(size_t)NT_FC*KC_FC*CHB];
static __device__ __align__(128) unsigned char g_WhhE_img[(size_t)RGRID*RW_BYTES];
static __device__ __align__(128) unsigned char g_WhhD_img[(size_t)RGRID*RW_BYTES];
static __device__ __align__(128) unsigned char g_hImg[2*IMGB];

static __device__ float g_gi_enc[(size_t)MENC*H3];
static __device__ float g_gi_dec[(size_t)MDEC*H3];
static __device__ float g_gic[BB*H3];
static __device__ float g_ctx[BB*HH];
static __device__ float g_Pc[BB*VV];
static __device__ unsigned g_arrive;

// ---------------- PTX helpers (baseline PTX only) ----------------
__device__ __forceinline__ uint32_t s2u(const void* p) {
    uint32_t a;
    asm("{ .reg .u64 t; cvta.to.shared.u64 t, %1; cvt.u32.u64 %0, t; }" : "=r"(a) : "l"(p));
    return a;
}
#define MBAR_INIT(a, c) asm volatile("mbarrier.init.shared.b64 [%0], %1;" :: "r"(a), "r"(c) : "memory")
#define MBAR_EXPECT_TX(a, b) asm volatile("mbarrier.arrive.expect_tx.shared.b64 _, [%0], %1;" :: "r"(a), "r"(b) : "memory")
#define MBAR_ARRIVE(a) asm volatile("mbarrier.arrive.shared.b64 _, [%0];" :: "r"(a) : "memory")

#define MBAR_WAIT(a, p) do { \
    uint32_t _m = (a), _p = (p), _d; \
    asm volatile("{\n\t.reg .pred q;\n\tmbarrier.try_wait.parity.acquire.cta.shared::cta.b64 q, [%1], %2;\n\tselp.b32 %0,1,0,q;\n\t}" \
        : "=r"(_d) : "r"(_m), "r"(_p) : "memory"); \
    if (!_d) { \
        asm volatile("{\n\t.reg .pred Q;\n\tWL_%=:\n\tmbarrier.try_wait.parity.acquire.cta.shared::cta.b64 Q, [%0], %1, 0x989680;\n\t@Q bra.uni WD_%=;\n\tbra.uni WL_%=;\n\tWD_%=:\n\t}" \
            :: "r"(_m), "r"(_p) : "memory"); \
    } \
} while (0)

#define MBAR_WAIT_RLX(a, p) do { \
    uint32_t _m = (a), _p = (p), _d; \
    asm volatile("{\n\t.reg .pred q;\n\tmbarrier.try_wait.parity.relaxed.cta.shared::cta.b64 q, [%1], %2, 0x989680;\n\tselp.b32 %0,1,0,q;\n\t}" \
        : "=r"(_d) : "r"(_m), "r"(_p) : "memory"); \
    if (!_d) { \
        asm volatile("{\n\t.reg .pred Q;\n\tWL_%=:\n\tmbarrier.try_wait.parity.relaxed.cta.shared::cta.b64 Q, [%0], %1, 0x989680;\n\t@Q bra.uni WD_%=;\n\tbra.uni WL_%=;\n\tWD_%=:\n\t}" \
            :: "r"(_m), "r"(_p) : "memory"); \
    } \
} while (0)

__device__ __forceinline__ void bulk_g2s(uint32_t dst, const void* src, uint32_t bytes, uint32_t mbar) {
    asm volatile("cp.async.bulk.shared::cluster.global.mbarrier::complete_tx::bytes [%0], [%1], %2, [%3];"
        :: "r"(dst), "l"(src), "r"(bytes), "r"(mbar) : "memory");
}

#define LDSM_X4(r0, r1, r2, r3, a) \
    asm volatile("ldmatrix.sync.aligned.m8n8.x4.shared.b16 {%0,%1,%2,%3}, [%4];" \
        : "=r"(r0), "=r"(r1), "=r"(r2), "=r"(r3) : "r"(a))
#define LDSM_X2(r0, r1, a) \
    asm volatile("ldmatrix.sync.aligned.m8n8.x2.shared.b16 {%0,%1}, [%2];" \
        : "=r"(r0), "=r"(r1) : "r"(a))

#define MMA16816(d, a0, a1, a2, a3, b0, b1) \
    asm volatile("mma.sync.aligned.m16n8k16.row.col.f32.bf16.bf16.f32 " \
        "{%0,%1,%2,%3}, {%4,%5,%6,%7}, {%8,%9}, {%0,%1,%2,%3};" \
        : "+f"((d)[0]), "+f"((d)[1]), "+f"((d)[2]), "+f"((d)[3]) \
        : "r"(a0), "r"(a1), "r"(a2), "r"(a3), "r"(b0), "r"(b1))

// fast gates (MUFU-based; ~2ulp, far below split error)
__device__ __forceinline__ float fast_sigmoid(float x) {
    return 1.f / (1.f + __expf(-x));
}
__device__ __forceinline__ float fast_tanh(float x) {
    float a = fminf(fmaxf(x, -15.f), 15.f);
    float e = __expf(-2.f * a);
    return (1.f - e) / (1.f + e);
}

// ---------------- tiny helpers ----------------
__global__ void k_reset_bar() { g_arrive = 0u; }

// ---------------- bf16 split + SW128 packing ----------------
__device__ __forceinline__ void split8(const float* a, uint4& H, uint4& L) {
    unsigned hv[4], lv[4];
#pragma unroll
    for (int j = 0; j < 4; j++) {
        __nv_bfloat16 h0 = __float2bfloat16(a[2*j]),   h1 = __float2bfloat16(a[2*j+1]);
        __nv_bfloat16 l0 = __float2bfloat16(a[2*j]   - __bfloat162float(h0));
        __nv_bfloat16 l1 = __float2bfloat16(a[2*j+1] - __bfloat162float(h1));
        hv[j] = (unsigned)__bfloat16_as_ushort(h0) | ((unsigned)__bfloat16_as_ushort(h1) << 16);
        lv[j] = (unsigned)__bfloat16_as_ushort(l0) | ((unsigned)__bfloat16_as_ushort(l1) << 16);
    }
    H = make_uint4(hv[0], hv[1], hv[2], hv[3]);
    L = make_uint4(lv[0], lv[1], lv[2], lv[3]);
}

__global__ void k_pack_X(const float* __restrict__ emb, const int* __restrict__ seq,
                         unsigned char* __restrict__ dst, int Mrows, int ACH) {
    int i = blockIdx.x * blockDim.x + threadIdx.x;
    int m = i >> 6;
    if (m >= Mrows) return;
    int k = (i & 63) * 8;
    int tok = seq[(m & 127) * LL + (m >> 7)];
    const float* s = emb + (size_t)tok * EE + k;
    float4 f0 = *(const float4*)s, f1 = *(const float4*)(s + 4);
    float a[8] = {f0.x, f0.y, f0.z, f0.w, f1.x, f1.y, f1.z, f1.w};
    uint4 H, L; split8(a, H, L);
    int mt = m >> 7, r = m & 127;
    int sw = SW128(r*128 + (k & 63)*2);
    int c0 = k >> 6;
    size_t tb = (size_t)mt * ACH * CHB;
    *(uint4*)(dst + tb + (size_t)(c0     ) * CHB + sw) = H;
    *(uint4*)(dst + tb + (size_t)(c0 + 8 ) * CHB + sw) = L;
    *(uint4*)(dst + tb + (size_t)(c0 + 16) * CHB + sw) = H;
}

__device__ __forceinline__ void packW_item(int i, const float* __restrict__ W, int ldw, int col0,
                                           unsigned char* __restrict__ dst, int Ksrc,
                                           int chunkbase, int KCtot) {
    int Kvec = Ksrc >> 3;
    int n = i / Kvec;
    int k = (i - n * Kvec) * 8;
    const float* s = W + (size_t)n * ldw + col0 + k;
    float4 f0 = *(const float4*)s, f1 = *(const float4*)(s + 4);
    float a[8] = {f0.x, f0.y, f0.z, f0.w, f1.x, f1.y, f1.z, f1.w};
    uint4 H, L; split8(a, H, L);
    int nt = n >> 7, r = n & 127;
    int sw = SW128(r*128 + (k & 63)*2);
    int c0 = k >> 6, KS = Ksrc >> 6;
    size_t tb = (size_t)nt * KCtot * CHB;
    *(uint4*)(dst + tb + (size_t)(chunkbase + c0        ) * CHB + sw) = H;
    *(uint4*)(dst + tb + (size_t)(chunkbase + KS + c0   ) * CHB + sw) = H;
    *(uint4*)(dst + tb + (size_t)(chunkbase + 2*KS + c0 ) * CHB + sw) = L;
}

__device__ __forceinline__ void packWhh_item(int i, const float* __restrict__ Whh,
                                             unsigned char* __restrict__ img) {
    int n = i >> 7;
    int k = (i & 127) * 8;
    int g = n >> 10, hcol = n & 1023;
    int blk = hcol >> 3, jj = hcol & 7;
    int rr = g*8 + jj;
    const float* s = Whh + (size_t)n * HH + k;
    float4 f0 = *(const float4*)s, f1 = *(const float4*)(s + 4);
    float a[8] = {f0.x, f0.y, f0.z, f0.w, f1.x, f1.y, f1.z, f1.w};
    uint4 H, L; split8(a, H, L);
    unsigned char* base = img + (size_t)blk * RW_BYTES;
    int sw = SW128(rr*128 + (k & 63)*2);
    *(uint4*)(base + (size_t)(k >> 6) * 3072 + sw) = H;
    *(uint4*)(base + (size_t)(16 + (k >> 6)) * 3072 + sw) = L;
}

// All weight packs in ONE launch.
#define J0 196608
#define J1 393216
#define J2 524288
#define J3 786432
#define J4 1179648
#define J5 1572864
__global__ void k_pack_Wall(const float* __restrict__ Wihe, const float* __restrict__ Wihd,
                            const float* __restrict__ fcW,
                            const float* __restrict__ WhhE, const float* __restrict__ WhhD,
                            unsigned char* __restrict__ WiheP, unsigned char* __restrict__ WihdP,
                            unsigned char* __restrict__ fcWP,
                            unsigned char* __restrict__ WhhEimg, unsigned char* __restrict__ WhhDimg) {
    int i = blockIdx.x * blockDim.x + threadIdx.x;
    if (i < J0)      { packW_item(i,      Wihe, EE,  0,  WiheP, EE, 0,  KC_GI); }
    else if (i < J1) { packW_item(i - J0, Wihd, EH,  0,  WihdP, EE, 0,  KC_GI); }
    else if (i < J2) { packW_item(i - J1, fcW,  E2H, 0,  fcWP,  EE, 0,  KC_FC); }
    else if (i < J3) { packW_item(i - J2, fcW,  E2H, EE, fcWP,  HH, 24, KC_FC); }
    else if (i < J4) { packWhh_item(i - J3, WhhE, WhhEimg); }
    else if (i < J5) { packWhh_item(i - J4, WhhD, WhhDimg); }
}

// ---------------- mma.sync bf16 GEMM (R8-proven: NST=4, 1 CTA/SM) ----------------
__global__ __launch_bounds__(288, 1)
void k_mmagemm(const unsigned char* __restrict__ Ap, int ACH,
               const unsigned char* __restrict__ Bp, int KC,
               const float* __restrict__ bias, float* __restrict__ C, int ldc,
               const float* __restrict__ Pc, float* __restrict__ outp, int mode) {
    extern __shared__ unsigned char smem[];
    uint32_t sb = s2u(smem);
    int tid = threadIdx.x, wid = tid >> 5, lane = tid & 31;
    int nt = blockIdx.x, mt = blockIdx.y;

    if (tid == 0) {
        for (int s = 0; s < NST; s++) { MBAR_INIT(sb + 8 + s*8, 1); MBAR_INIT(sb + 40 + s*8, 8); }
    }
    __syncthreads();

    const unsigned char* Ab = Ap + (size_t)mt * ACH * CHB;
    const unsigned char* Bb = Bp + (size_t)nt * KC * CHB;

    if (wid == 8) {
        if (lane == 0) {
            for (int kc = 0; kc < KC; kc++) {
                int s = kc & (NST - 1);
                int eph = (((kc >> 2) & 1)) ^ 1;
                MBAR_WAIT_RLX(sb + 40 + s*8, eph);
                MBAR_EXPECT_TX(sb + 8 + s*8, 2*CHB);
                bulk_g2s(sb + 1024 + s*STB,       Ab + (size_t)kc*CHB, CHB, sb + 8 + s*8);
                bulk_g2s(sb + 1024 + s*STB + CHB, Bb + (size_t)kc*CHB, CHB, sb + 8 + s*8);
            }
        }
        return;
    }

    int wm = wid & 1, wn = wid >> 1;
    float d[4][4][4];
#pragma unroll
    for (int i = 0; i < 4; i++)
#pragma unroll
        for (int j = 0; j < 4; j++)
#pragma unroll
            for (int q = 0; q < 4; q++) d[i][j][q] = 0.f;

    int arow = lane & 15;
    int ahalf = (lane >> 4) * 16;
    int axm = (arow & 7) << 4;
    uint32_t aRow128[4];
#pragma unroll
    for (int i = 0; i < 4; i++) aRow128[i] = (uint32_t)(wm*64 + i*16 + arow) * 128;
    int bg = lane >> 3;
    int bn7 = lane & 7;
    int bxm = bn7 << 4;
    int bkadd = (bg & 1) * 16;
    uint32_t bRow128[2];
#pragma unroll
    for (int q = 0; q < 2; q++) bRow128[q] = (uint32_t)(wn*32 + q*16 + (bg>>1)*8 + bn7) * 128;

    for (int kc = 0; kc < KC; kc++) {
        int s = kc & (NST - 1);
        int ph = (kc >> 2) & 1;
        MBAR_WAIT(sb + 8 + s*8, ph);
        uint32_t Abase = sb + 1024 + s*STB;
        uint32_t Bbase = Abase + CHB;
#pragma unroll
        for (int ks = 0; ks < 4; ks++) {
            int kb = ks * 32;
            uint32_t afr[4][4], bfr[2][4];
#pragma unroll
            for (int i = 0; i < 4; i++) {
                uint32_t addr = Abase + aRow128[i] + (uint32_t)((kb + ahalf) ^ axm);
                LDSM_X4(afr[i][0], afr[i][1], afr[i][2], afr[i][3], addr);
            }
#pragma unroll
            for (int q = 0; q < 2; q++) {
                uint32_t addr = Bbase + bRow128[q] + (uint32_t)((kb + bkadd) ^ bxm);
                LDSM_X4(bfr[q][0], bfr[q][1], bfr[q][2], bfr[q][3], addr);
            }
#pragma unroll
            for (int i = 0; i < 4; i++)
#pragma unroll
                for (int j = 0; j < 4; j++)
                    MMA16816(d[i][j], afr[i][0], afr[i][1], afr[i][2], afr[i][3],
                             bfr[j>>1][(j&1)*2], bfr[j>>1][(j&1)*2 + 1]);
        }
        __syncwarp();
        if (lane == 0) MBAR_ARRIVE(sb + 40 + s*8);
    }

    int lr = lane >> 2;
    int lc = (lane & 3) * 2;
#pragma unroll
    for (int i = 0; i < 4; i++) {
        int r0 = wm*64 + i*16 + lr;
#pragma unroll
        for (int j = 0; j < 4; j++) {
            int c = nt*128 + wn*32 + j*8 + lc;
            if (mode == 0) {
                float2 bv = *(const float2*)(bias + c);
                float* cp0 = C + (size_t)(mt*128 + r0) * ldc + c;
                float* cp1 = C + (size_t)(mt*128 + r0 + 8) * ldc + c;
                *(float2*)cp0 = make_float2(d[i][j][0] + bv.x, d[i][j][1] + bv.y);
                *(float2*)cp1 = make_float2(d[i][j][2] + bv.x, d[i][j][3] + bv.y);
            } else {
                float2 p0 = *(const float2*)(Pc + (size_t)r0 * VV + c);
                float2 p1 = *(const float2*)(Pc + (size_t)(r0 + 8) * VV + c);
                float* op0 = outp + ((size_t)r0 * LL + (mt + 1)) * VV + c;
                float* op1 = outp + ((size_t)(r0 + 8) * LL + (mt + 1)) * VV + c;
                *(float2*)op0 = make_float2(d[i][j][0] + p0.x, d[i][j][1] + p0.y);
                *(float2*)op1 = make_float2(d[i][j][2] + p1.x, d[i][j][3] + p1.y);
            }
        }
    }
}

// ---------------- small fp32 GEMM (context one-shots) ----------------
__global__ __launch_bounds__(256) void k_gemm(
    const float* __restrict__ A, int lda,
    const float* __restrict__ Bw, int ldb, int bofs,
    const float* __restrict__ bias,
    float* __restrict__ C, int N, int K)
{
    __shared__ float As[16][132];
    __shared__ float Bs[16][68];
    const int m0 = blockIdx.y * 128;
    const int n0 = blockIdx.x * 64;
    const int tid = threadIdx.x;
    const int rg = tid >> 4, cg = tid & 15;
    float acc[8][4];
#pragma unroll
    for (int i = 0; i < 8; i++)
#pragma unroll
        for (int j = 0; j < 4; j++) acc[i][j] = 0.f;
    const int r0 = tid >> 2, r1 = r0 + 64;
    const int kq0 = (tid & 3) * 4;
    const size_t aoff0 = (size_t)(m0+r0) * lda;
    const size_t aoff1 = (size_t)(m0+r1) * lda;
    const size_t boff  = (size_t)(n0 + r0) * ldb + bofs;
    for (int k0 = 0; k0 < K; k0 += 16) {
        float4 va0 = *reinterpret_cast<const float4*>(A + aoff0 + k0 + kq0);
        float4 va1 = *reinterpret_cast<const float4*>(A + aoff1 + k0 + kq0);
        float4 vb  = *reinterpret_cast<const float4*>(Bw + boff + k0 + kq0);
        As[kq0+0][r0] = va0.x; As[kq0+1][r0] = va0.y; As[kq0+2][r0] = va0.z; As[kq0+3][r0] = va0.w;
        As[kq0+0][r1] = va1.x; As[kq0+1][r1] = va1.y; As[kq0+2][r1] = va1.z; As[kq0+3][r1] = va1.w;
        Bs[kq0+0][r0] = vb.x;  Bs[kq0+1][r0] = vb.y;  Bs[kq0+2][r0] = vb.z;  Bs[kq0+3][r0] = vb.w;
        __syncthreads();
#pragma unroll
        for (int kk = 0; kk < 16; kk++) {
            float4 a0 = *reinterpret_cast<const float4*>(&As[kk][rg*8]);
            float4 a1 = *reinterpret_cast<const float4*>(&As[kk][rg*8+4]);
            float4 b  = *reinterpret_cast<const float4*>(&Bs[kk][cg*4]);
            float av[8] = {a0.x,a0.y,a0.z,a0.w,a1.x,a1.y,a1.z,a1.w};
            float bv[4] = {b.x,b.y,b.z,b.w};
#pragma unroll
            for (int i = 0; i < 8; i++)
#pragma unroll
                for (int j = 0; j < 4; j++) acc[i][j] += av[i]*bv[j];
        }
        __syncthreads();
    }
    float4 bb = make_float4(0.f,0.f,0.f,0.f);
    if (bias) bb = *reinterpret_cast<const float4*>(bias + n0 + cg*4);
#pragma unroll
    for (int i = 0; i < 8; i++) {
        float* cp = C + (size_t)(m0 + rg*8 + i) * N + n0 + cg*4;
        *reinterpret_cast<float4*>(cp) =
            make_float4(acc[i][0]+bb.x, acc[i][1]+bb.y, acc[i][2]+bb.z, acc[i][3]+bb.w);
    }
}

// ---------------- grid barrier (128 arrivals) ----------------
__device__ __forceinline__ void grid_bar(unsigned want) {
    __threadfence();
    __syncthreads();
    if (threadIdx.x == 0) {
        atomicAdd(&g_arrive, 1u);
        volatile unsigned* p = &g_arrive;
        while (*p < want) { }
    }
    __syncthreads();
}

// ---------------- tensor-core persistent GRU recurrence (R13-proven: 2-way K-split) ----------------
// 128 blocks x 288 threads: 8 compute warps + producer warp 8.
// Warp pair (2p, 2p+1) owns batch rows p*32..p*32+31; each warp processes only
// chunks with (c & 1) == (wid & 1), halving W ldsm traffic. Accumulator frags
// exchanged through smem (12KB) + named barrier before the GRU elementwise.
__global__ __launch_bounds__(288, 1)
void k_rec_tc(const unsigned char* __restrict__ Wimg,
              const float* __restrict__ gi, const float* __restrict__ gic,
              unsigned char* __restrict__ imgBase,
              const float* __restrict__ bhh,
              const float* __restrict__ ctx_init,
              float* __restrict__ ctx_out,
              unsigned char* __restrict__ fcpack,
              int T)
{
    extern __shared__ unsigned char smem[];
    uint32_t sb = s2u(smem);
    int tid = threadIdx.x, wid = tid >> 5, lane = tid & 31;
    int bid = blockIdx.x;
    int j0 = bid * 8;
    int sub = wid & 1;

    if (tid == 0) {
        for (int s = 0; s < RNST; s++) { MBAR_INIT(sb + 16 + s*8, 1); MBAR_INIT(sb + 80 + s*8, 4); }
        MBAR_INIT(sb + 144, 1);
    }
    __syncthreads();

    uint32_t ringb = sb + 1024;
    uint32_t wsm   = sb + 1024 + RNST*RCH;
    float*   red   = (float*)(smem + 1024 + RNST*RCH + RW_BYTES);

    if (wid == 8 && lane == 0) {
        MBAR_EXPECT_TX(sb + 144, RW_BYTES);
        bulk_g2s(wsm, Wimg + (size_t)bid * RW_BYTES, RW_BYTES, sb + 144);
    }

    int lr = lane >> 2, lc2 = (lane & 3) * 2;
    int chnk = j0 >> 6;
    int cbyte = ((j0 + lc2) & 63) * 2;
    float ho[2][2];
    float2 gx[2][3];
    float2 bh2[3];

    if (wid < 8) {
#pragma unroll
        for (int g = 0; g < 3; g++) bh2[g] = *(const float2*)(bhh + g*HH + j0 + lc2);
#pragma unroll
        for (int h = 0; h < 2; h++) {
            int b = wid*16 + h*8 + lr;
            if (ctx_init) {
                float2 c = __ldcg((const float2*)(ctx_init + (size_t)b*HH + j0 + lc2));
                ho[h][0] = c.x; ho[h][1] = c.y;
            } else { ho[h][0] = 0.f; ho[h][1] = 0.f; }
            if (gic) {
#pragma unroll
                for (int g = 0; g < 3; g++)
                    gx[h][g] = *(const float2*)(gic + (size_t)b*H3 + g*HH + j0 + lc2);
            } else {
#pragma unroll
                for (int g = 0; g < 3; g++) gx[h][g] = make_float2(0.f, 0.f);
            }
            if (!ctx_init) {
                unsigned sw = SW128((unsigned)(b*128 + cbyte));
                __stcg((unsigned*)(imgBase + (size_t)chnk*RCH + sw), 0u);
                __stcg((unsigned*)(imgBase + (size_t)(16+chnk)*RCH + sw), 0u);
            }
        }
    }
    grid_bar(1u * RGRID);
    if (wid < 8) MBAR_WAIT(sb + 144, 0);

    int arow = lane & 15, ahalf = (lane >> 4) * 16, axm = (arow & 7) << 4;
    uint32_t aR[2];
#pragma unroll
    for (int i = 0; i < 2; i++)
        aR[i] = (uint32_t)((wid >> 1)*32 + i*16 + arow) * 128;  // (garbage for wid==8, unused)
    int b4row = (lane >> 4)*8 + (lane & 7);
    int b4k   = ((lane >> 3) & 1) * 16;
    int b4xm  = (b4row & 7) << 4;
    int b2row = 16 + (lane & 7);
    int b2k   = ((lane >> 3) & 1) * 16;
    int b2xm  = (b2row & 7) << 4;

    for (int t = 0; t < T; t++) {
        const unsigned char* img_r = imgBase + (size_t)(t & 1) * IMGB;
        unsigned char*       img_w = imgBase + (size_t)((t + 1) & 1) * IMGB;

        if (wid == 8) {
            if (lane == 0) {
                for (int c = 0; c < RNCH; c++) {
                    unsigned idx = (unsigned)t * RNCH + c;
                    int s = idx & (RNST - 1);
                    int eph = ((idx >> 2) & 1) ^ 1;
                    MBAR_WAIT_RLX(sb + 80 + s*8, eph);
                    MBAR_EXPECT_TX(sb + 16 + s*8, RCH);
                    bulk_g2s(ringb + s*RCH, img_r + (size_t)c*RCH, RCH, sb + 16 + s*8);
                }
            }
        } else {
            float2 gv[2][3];
#pragma unroll
            for (int h = 0; h < 2; h++) {
                int b = wid*16 + h*8 + lr;
                const float* gb = gi + ((size_t)t*BB + b)*H3 + j0 + lc2;
#pragma unroll
                for (int g = 0; g < 3; g++)
                    gv[h][g] = __ldcg((const float2*)(gb + g*HH));
            }

            float d[2][3][4];
#pragma unroll
            for (int i = 0; i < 2; i++)
#pragma unroll
                for (int nf = 0; nf < 3; nf++)
#pragma unroll
                    for (int q = 0; q < 4; q++) d[i][nf][q] = 0.f;

            // process only chunks of this warp's parity
            for (int c = sub; c < RNCH; c += 2) {
                unsigned idx = (unsigned)t * RNCH + c;
                int s = idx & (RNST - 1);
                int fph = (idx >> 2) & 1;
                MBAR_WAIT(sb + 16 + s*8, fph);
                uint32_t Abase = ringb + s*RCH;
                int cw = (c < 16) ? c : (c - 16);
                uint32_t Wh = wsm + (uint32_t)cw * 3072;
#pragma unroll
                for (int ks = 0; ks < 4; ks++) {
                    int kb = ks * 32;
                    uint32_t a0[2], a1[2], a2[2], a3[2];
#pragma unroll
                    for (int i = 0; i < 2; i++)
                        LDSM_X4(a0[i], a1[i], a2[i], a3[i],
                                Abase + aR[i] + (uint32_t)((kb + ahalf) ^ axm));
                    uint32_t b0,b1,b2,b3,b4,b5;
                    LDSM_X4(b0,b1,b2,b3, Wh + (uint32_t)(b4row*128) + (uint32_t)((kb + b4k) ^ b4xm));
                    LDSM_X2(b4,b5,       Wh + (uint32_t)(b2row*128) + (uint32_t)((kb + b2k) ^ b2xm));
#pragma unroll
                    for (int i = 0; i < 2; i++) {
                        MMA16816(d[i][0], a0[i], a1[i], a2[i], a3[i], b0, b1);
                        MMA16816(d[i][1], a0[i], a1[i], a2[i], a3[i], b2, b3);
                        MMA16816(d[i][2], a0[i], a1[i], a2[i], a3[i], b4, b5);
                    }
                    if (c < 16) {
                        uint32_t Wl = wsm + (uint32_t)(16 + c) * 3072;
                        LDSM_X4(b0,b1,b2,b3, Wl + (uint32_t)(b4row*128) + (uint32_t)((kb + b4k) ^ b4xm));
                        LDSM_X2(b4,b5,       Wl + (uint32_t)(b2row*128) + (uint32_t)((kb + b2k) ^ b2xm));
#pragma unroll
                        for (int i = 0; i < 2; i++) {
                            MMA16816(d[i][0], a0[i], a1[i], a2[i], a3[i], b0, b1);
                            MMA16816(d[i][1], a0[i], a1[i], a2[i], a3[i], b2, b3);
                            MMA16816(d[i][2], a0[i], a1[i], a2[i], a3[i], b4, b5);
                        }
                    }
                }
                __syncwarp();
                if (lane == 0) MBAR_ARRIVE(sb + 80 + s*8);
            }

            // exchange the accumulator frag we don't own with our pair partner.
            {
                float* wr = red + (wid*32 + lane)*12;
#pragma unroll
                for (int nf = 0; nf < 3; nf++)
#pragma unroll
                    for (int q = 0; q < 4; q++)
                        wr[nf*4 + q] = sub ? d[0][nf][q] : d[1][nf][q];
            }
            asm volatile("bar.sync 1, 256;" ::: "memory");
            float dd[3][4];
            {
                const float* pr = red + ((wid ^ 1)*32 + lane)*12;
#pragma unroll
                for (int nf = 0; nf < 3; nf++)
#pragma unroll
                    for (int q = 0; q < 4; q++)
                        dd[nf][q] = (sub ? d[1][nf][q] : d[0][nf][q]) + pr[nf*4 + q];
            }

            // GRU elementwise (fast MUFU gates); critical-path img stores first
            unsigned hiw_s[2], low_s[2];
#pragma unroll
            for (int h = 0; h < 2; h++) {
#pragma unroll
                for (int c2 = 0; c2 < 2; c2++) {
                    int q = h*2 + c2;
                    float gr = (c2 ? gv[h][0].y : gv[h][0].x) + (c2 ? gx[h][0].y : gx[h][0].x);
                    float gz = (c2 ? gv[h][1].y : gv[h][1].x) + (c2 ? gx[h][1].y : gx[h][1].x);
                    float gn = (c2 ? gv[h][2].y : gv[h][2].x) + (c2 ? gx[h][2].y : gx[h][2].x);
                    float hr = dd[0][q] + (c2 ? bh2[0].y : bh2[0].x);
                    float hz = dd[1][q] + (c2 ? bh2[1].y : bh2[1].x);
                    float hn = dd[2][q] + (c2 ? bh2[2].y : bh2[2].x);
                    float rr = fast_sigmoid(gr + hr);
                    float zz = fast_sigmoid(gz + hz);
                    float nn = fast_tanh(gn + rr * hn);
                    ho[h][c2] = (1.f - zz) * nn + zz * ho[h][c2];
                }
                __nv_bfloat16 h0b = __float2bfloat16(ho[h][0]);
                __nv_bfloat16 h1b = __float2bfloat16(ho[h][1]);
                __nv_bfloat16 l0b = __float2bfloat16(ho[h][0] - __bfloat162float(h0b));
                __nv_bfloat16 l1b = __float2bfloat16(ho[h][1] - __bfloat162float(h1b));
                unsigned hiw = (unsigned)__bfloat16_as_ushort(h0b) | ((unsigned)__bfloat16_as_ushort(h1b) << 16);
                unsigned low = (unsigned)__bfloat16_as_ushort(l0b) | ((unsigned)__bfloat16_as_ushort(l1b) << 16);
                int b = wid*16 + h*8 + lr;
                unsigned sw = SW128((unsigned)(b*128 + cbyte));
                __stcg((unsigned*)(img_w + (size_t)chnk*RCH + sw), hiw);
                __stcg((unsigned*)(img_w + (size_t)(16+chnk)*RCH + sw), low);
                hiw_s[h] = hiw; low_s[h] = low;
            }
#pragma unroll
            for (int h = 0; h < 2; h++) {
                int b = wid*16 + h*8 + lr;
                unsigned sw = SW128((unsigned)(b*128 + cbyte));
                if (fcpack) {
                    size_t tb2 = (size_t)t * KC_FC * CHB;
                    __stcg((unsigned*)(fcpack + tb2 + (size_t)(24+chnk)*CHB + sw), hiw_s[h]);
                    __stcg((unsigned*)(fcpack + tb2 + (size_t)(40+chnk)*CHB + sw), low_s[h]);
                    __stcg((unsigned*)(fcpack + tb2 + (size_t)(56+chnk)*CHB + sw), hiw_s[h]);
                }
                if (ctx_out && t == T-1)
                    __stcg((float2*)(ctx_out + (size_t)b*HH + j0 + lc2),
                           make_float2(ho[h][0], ho[h][1]));
            }
        }
        grid_bar((unsigned)(t + 2) * RGRID);
    }
}

// ---------------- small output pieces ----------------
__global__ void k_out_small(float* __restrict__ out) {
    int i = blockIdx.x * blockDim.x + threadIdx.x;
    const size_t NOUT = (size_t)BB * LL * VV;
    if (i < BB * VV) {
        int b = i / VV, v = i % VV;
        out[(size_t)b * LL * VV + v] = 0.f;
    }
    if (i < 3 * BB * HH) {
        out[NOUT + i] = (i < BB * HH) ? g_ctx[i] : 0.f;
    }
}

// ---------------- launch ----------------
extern "C" void kernel_launch(void* const* d_in, const int* in_sizes, int n_in,
                              void* d_out, int out_size) {
    const int*   seq     = (const int*)  d_in[0];
    const float* emb_enc = (const float*)d_in[2];
    const float* W_ih_e  = (const float*)d_in[3];
    const float* W_hh_e  = (const float*)d_in[4];
    const float* b_ih_e  = (const float*)d_in[5];
    const float* b_hh_e  = (const float*)d_in[6];
    const float* emb_dec = (const float*)d_in[7];
    const float* W_ih_d  = (const float*)d_in[8];
    const float* W_hh_d  = (const float*)d_in[9];
    const float* b_ih_d  = (const float*)d_in[10];
    const float* b_hh_d  = (const float*)d_in[11];
    const float* fc_W    = (const float*)d_in[12];
    const float* fc_b    = (const float*)d_in[13];

    void* p;
    cudaGetSymbolAddress(&p, g_gi_enc);  float* gi_enc = (float*)p;
    cudaGetSymbolAddress(&p, g_gi_dec);  float* gi_dec = (float*)p;
    cudaGetSymbolAddress(&p, g_gic);     float* gic = (float*)p;
    cudaGetSymbolAddress(&p, g_ctx);     float* ctx = (float*)p;
    cudaGetSymbolAddress(&p, g_Pc);      float* Pc = (float*)p;
    cudaGetSymbolAddress(&p, g_Xenc_p);  unsigned char* Xenc_p = (unsigned char*)p;
    cudaGetSymbolAddress(&p, g_fcin_p);  unsigned char* fcin_p = (unsigned char*)p;
    cudaGetSymbolAddress(&p, g_Wihe_p);  unsigned char* Wihe_p = (unsigned char*)p;
    cudaGetSymbolAddress(&p, g_Wihd_p);  unsigned char* Wihd_p = (unsigned char*)p;
    cudaGetSymbolAddress(&p, g_fcW_p);   unsigned char* fcW_p = (unsigned char*)p;
    cudaGetSymbolAddress(&p, g_WhhE_img); unsigned char* WhhE = (unsigned char*)p;
    cudaGetSymbolAddress(&p, g_WhhD_img); unsigned char* WhhD = (unsigned char*)p;
    cudaGetSymbolAddress(&p, g_hImg);     unsigned char* hImg = (unsigned char*)p;

    cudaFuncSetAttribute(k_mmagemm, cudaFuncAttributeMaxDynamicSharedMemorySize, SMEMSZ);
    cudaFuncSetAttribute(k_rec_tc,  cudaFuncAttributeMaxDynamicSharedMemorySize, RSM);

    static cudaStream_t s2 = nullptr;
    static cudaEvent_t e1 = nullptr, e2 = nullptr, e3 = nullptr, e4 = nullptr;
    if (!s2) {
        cudaStreamCreateWithFlags(&s2, cudaStreamNonBlocking);
        cudaEventCreateWithFlags(&e1, cudaEventDisableTiming);
        cudaEventCreateWithFlags(&e2, cudaEventDisableTiming);
        cudaEventCreateWithFlags(&e3, cudaEventDisableTiming);
        cudaEventCreateWithFlags(&e4, cudaEventDisableTiming);
    }

    // 0,1) input packs
    k_pack_X<<<(MENC*64 + 255)/256, 256>>>(emb_enc, seq, Xenc_p, MENC, KC_GI);
    k_pack_X<<<(MDEC*64 + 255)/256, 256>>>(emb_dec, seq, fcin_p, MDEC, KC_FC);
    // 2) all weight packs
    k_pack_Wall<<<(J5 + 255)/256, 256>>>(W_ih_e, W_ih_d, fc_W, W_hh_e, W_hh_d,
                                         Wihe_p, Wihd_p, fcW_p, WhhE, WhhD);
    // 3) encoder input-gate GEMM
    k_mmagemm<<<dim3(NT_GI, MT_ENC), 288, SMEMSZ>>>(Xenc_p, KC_GI, Wihe_p, KC_GI, b_ih_e, gi_enc, H3, nullptr, nullptr, 0);
    // 4) barrier reset
    k_reset_bar<<<1, 1>>>();
    cudaEventRecord(e1, 0);

    // 5) encoder recurrence FIRST (grid=128 lands on SMs immediately)
    k_rec_tc<<<RGRID, 288, RSM>>>(WhhE, gi_enc, nullptr, hImg, b_hh_e, nullptr, ctx, nullptr, LL);
    cudaEventRecord(e3, 0);   // ctx ready after enc rec

    // Fork: decoder input-gate GEMM in s2 fills the ~20 SMs the rec leaves free.
    cudaStreamWaitEvent(s2, e1, 0);
    k_mmagemm<<<dim3(NT_GI, MT_DEC), 288, SMEMSZ, s2>>>(fcin_p, KC_FC, Wihd_p, KC_GI, b_ih_d, gi_dec, H3, nullptr, nullptr, 0);
    cudaEventRecord(e2, s2);

    // Pc one-shot moved to s2: overlaps the decoder recurrence (needs ctx only).
    cudaStreamWaitEvent(s2, e3, 0);
    k_gemm<<<dim3(VV/64, 1), 256, 0, s2>>>(ctx, HH, fc_W, E2H, EE + HH, fc_b, Pc, VV, HH);
    cudaEventRecord(e4, s2);

    // 6) gic one-shot on main (true critical path: enc_rec -> gic -> dec_rec)
    k_gemm<<<dim3(H3/64, 1), 256>>>(ctx, HH, W_ih_d, EH, EE, nullptr, gic, H3, HH);
    // 7) barrier reset
    k_reset_bar<<<1, 1>>>();

    // Join: decoder recurrence consumes gi_dec produced in s2.
    cudaStreamWaitEvent(0, e2, 0);
    // 8) decoder recurrence (packs h2 into fcin chunks 24..71)
    k_rec_tc<<<RGRID, 288, RSM>>>(WhhD, gi_dec, gic, hImg, b_hh_d, ctx, nullptr, fcin_p, LDEC);
    // 9) fused fc GEMM -> d_out (needs Pc from s2)
    cudaStreamWaitEvent(0, e4, 0);
    k_mmagemm<<<dim3(NT_FC, MT_DEC), 288, SMEMSZ>>>(fcin_p, KC_FC, fcW_p, KC_FC, nullptr, nullptr, 0, Pc, (float*)d_out, 1);
    // 10) small output pieces
    k_out_small<<<(3*BB*HH + 255)/256, 256>>>((float*)d_out);
}